// round 2
// baseline (speedup 1.0000x reference)
#include <cuda_runtime.h>
#include <cstdint>

// Problem constants (fixed by the dataset)
#define N_NODES  50000
#define N_EDGES  800000
#define IN_C     768
#define HID      256
#define OUT_C    128
#define N_GRAPHS 256
#define F_TOT    384            // HID + OUT_C (node/graph embed width)
#define F4_TOT   96             // F_TOT/4

// ---------------------------------------------------------------------------
// Scratch (device globals -- no runtime allocation allowed)
// ---------------------------------------------------------------------------
__device__ float g_h   [N_NODES * HID];    // layer1 pre-agg h = x@W1 ; reused as h2pre (first N*128)
__device__ float g_h1  [N_NODES * HID];    // layer1 agg -> h1 (post relu, kept for layer2)
__device__ float g_agg2[N_NODES * OUT_C];  // layer2 agg -> h2
__device__ float g_deg [N_NODES];
__device__ float g_dinv[N_NODES];
__device__ float g_pool[N_GRAPHS * F_TOT];
__device__ float g_cnt [N_GRAPHS];
__device__ int   g_idx64;                  // 1 if edge_index/batch are int64, 0 if int32

// ---------------------------------------------------------------------------
// Helpers
// ---------------------------------------------------------------------------
__device__ __forceinline__ int load_idx(const void* p, long long i) {
    if (g_idx64) return (int)((const long long*)p)[i];
    return ((const int*)p)[i];
}

__device__ __forceinline__ void red_add_v4(float* p, float x, float y, float z, float w) {
    asm volatile("red.global.add.v4.f32 [%0], {%1,%2,%3,%4};"
                 :: "l"(p), "f"(x), "f"(y), "f"(z), "f"(w) : "memory");
}

// ---------------------------------------------------------------------------
// dtype detection: interpret first 256 entries of edge_index as int64.
// If data is really int32, pairs (v0,v1) read as v0 + v1*2^32 which is out of
// [0, N_NODES) unless v1 == 0 (prob ~2e-5 per entry) -> detection is robust.
// ---------------------------------------------------------------------------
__global__ void k_detect(const void* ei) {
    if (threadIdx.x == 0 && blockIdx.x == 0) {
        const long long* p = (const long long*)ei;
        int ok = 1;
        for (int i = 0; i < 256; i++) {
            long long v = p[i];
            if (v < 0 || v >= N_NODES) { ok = 0; break; }
        }
        g_idx64 = ok;
    }
}

__global__ void k_zero() {
    int i = blockIdx.x * blockDim.x + threadIdx.x;
    if (i < N_NODES) g_deg[i] = 0.f;
    if (i < N_GRAPHS * F_TOT) g_pool[i] = 0.f;
    if (i < N_GRAPHS) g_cnt[i] = 0.f;
}

__global__ void k_deg(const void* __restrict__ ei) {
    int e = blockIdx.x * blockDim.x + threadIdx.x;
    if (e < N_EDGES) {
        int d = load_idx(ei, (long long)N_EDGES + e);
        atomicAdd(&g_deg[d], 1.0f);
    }
}

__global__ void k_dinv() {
    int i = blockIdx.x * blockDim.x + threadIdx.x;
    if (i < N_NODES) g_dinv[i] = rsqrtf(g_deg[i] + 1.0f);
}

__global__ void k_cnt(const void* __restrict__ batch) {
    int i = blockIdx.x * blockDim.x + threadIdx.x;
    if (i < N_NODES) {
        int g = load_idx(batch, i);
        atomicAdd(&g_cnt[g], 1.0f);
    }
}

// ---------------------------------------------------------------------------
// Tiled fp32 SGEMM: C[M,N] = A[M,K] @ B[K,N].  BM=BN=128, BK=16, 256 thr,
// 8x8 micro-tile per thread. Requires K%16==0, N%128==0 (true here).
// ---------------------------------------------------------------------------
__global__ void __launch_bounds__(256)
k_sgemm(const float* __restrict__ A, const float* __restrict__ B,
        float* __restrict__ C, int M, int N, int K) {
    constexpr int BM = 128, BN = 128, BK = 16;
    __shared__ float As[BK][BM];
    __shared__ float Bs[BK][BN];

    const int tid  = threadIdx.x;
    const int trow = tid >> 4;          // 0..15
    const int tcol = tid & 15;          // 0..15
    const int mBase = blockIdx.y * BM;
    const int nBase = blockIdx.x * BN;

    float acc[8][8];
#pragma unroll
    for (int i = 0; i < 8; i++)
#pragma unroll
        for (int j = 0; j < 8; j++) acc[i][j] = 0.f;

    const int aRow = tid >> 2;          // 0..63  (4 float4 per 16-wide row)
    const int aCol = (tid & 3) << 2;    // 0,4,8,12
    const int bRow = tid >> 5;          // 0..7
    const int bCol = (tid & 31) << 2;   // 0..124

    for (int k0 = 0; k0 < K; k0 += BK) {
#pragma unroll
        for (int r = 0; r < 2; r++) {
            int m  = aRow + r * 64;
            int gm = mBase + m;
            float4 v = make_float4(0.f, 0.f, 0.f, 0.f);
            if (gm < M) v = *(const float4*)(A + (size_t)gm * K + k0 + aCol);
            As[aCol + 0][m] = v.x; As[aCol + 1][m] = v.y;
            As[aCol + 2][m] = v.z; As[aCol + 3][m] = v.w;
        }
#pragma unroll
        for (int r = 0; r < 2; r++) {
            int kk = bRow + r * 8;
            *(float4*)&Bs[kk][bCol] =
                *(const float4*)(B + (size_t)(k0 + kk) * N + nBase + bCol);
        }
        __syncthreads();
#pragma unroll
        for (int kk = 0; kk < BK; kk++) {
            float a[8], b[8];
            *(float4*)(a)     = *(float4*)&As[kk][trow * 8];
            *(float4*)(a + 4) = *(float4*)&As[kk][trow * 8 + 4];
            *(float4*)(b)     = *(float4*)&Bs[kk][tcol * 8];
            *(float4*)(b + 4) = *(float4*)&Bs[kk][tcol * 8 + 4];
#pragma unroll
            for (int i = 0; i < 8; i++)
#pragma unroll
                for (int j = 0; j < 8; j++)
                    acc[i][j] = fmaf(a[i], b[j], acc[i][j]);
        }
        __syncthreads();
    }

#pragma unroll
    for (int i = 0; i < 8; i++) {
        int gm = mBase + trow * 8 + i;
        if (gm < M) {
            float* cp = C + (size_t)gm * N + nBase + tcol * 8;
            *(float4*)(cp)     = make_float4(acc[i][0], acc[i][1], acc[i][2], acc[i][3]);
            *(float4*)(cp + 4) = make_float4(acc[i][4], acc[i][5], acc[i][6], acc[i][7]);
        }
    }
}

// ---------------------------------------------------------------------------
// agg[i] = h[i] * dinv[i]^2  (self-loop term). F4 = F/4 floats4 per node.
// ---------------------------------------------------------------------------
template <int SH>   // F4 = 1<<SH
__global__ void k_selfloop(const float* __restrict__ h, float* __restrict__ agg) {
    int tid = blockIdx.x * blockDim.x + threadIdx.x;
    if (tid >= (N_NODES << SH)) return;
    int i = tid >> SH;
    float di = g_dinv[i];
    float s  = di * di;
    float4 v = ((const float4*)h)[tid];
    v.x *= s; v.y *= s; v.z *= s; v.w *= s;
    ((float4*)agg)[tid] = v;
}

// ---------------------------------------------------------------------------
// Edge scatter: agg[dst] += h[src] * dinv[src]*dinv[dst]
// One thread per (edge, float4-chunk); 1<<SH chunks per edge.
// ---------------------------------------------------------------------------
template <int SH>
__global__ void __launch_bounds__(256)
k_scatter(const float* __restrict__ h, float* __restrict__ agg,
          const void* __restrict__ ei) {
    long long tid = (long long)blockIdx.x * blockDim.x + threadIdx.x;
    long long e = tid >> SH;
    if (e >= N_EDGES) return;
    int c = (int)(tid & ((1 << SH) - 1));
    int s = load_idx(ei, e);
    int d = load_idx(ei, (long long)N_EDGES + e);
    float nrm = g_dinv[s] * g_dinv[d];
    float4 v = ((const float4*)h)[((long long)s << SH) + c];
    float* dstp = agg + ((((long long)d << SH) + c) << 2);
    red_add_v4(dstp, v.x * nrm, v.y * nrm, v.z * nrm, v.w * nrm);
}

// ---------------------------------------------------------------------------
// Finalize: h = relu(agg + bias); write node_embed slice; red into pool sums.
// ---------------------------------------------------------------------------
template <int SH, int COFF, bool STORE_BACK>
__global__ void k_finalize(float* __restrict__ agg, const float* __restrict__ bias,
                           const void* __restrict__ batch, float* __restrict__ out_node) {
    int tid = blockIdx.x * blockDim.x + threadIdx.x;
    if (tid >= (N_NODES << SH)) return;
    int i = tid >> SH;
    int c = tid & ((1 << SH) - 1);
    float4 a  = ((float4*)agg)[tid];
    float4 bb = ((const float4*)bias)[c];
    a.x = fmaxf(a.x + bb.x, 0.f);
    a.y = fmaxf(a.y + bb.y, 0.f);
    a.z = fmaxf(a.z + bb.z, 0.f);
    a.w = fmaxf(a.w + bb.w, 0.f);
    if (STORE_BACK) ((float4*)agg)[tid] = a;
    ((float4*)out_node)[(long long)i * F4_TOT + COFF + c] = a;
    int g = load_idx(batch, i);
    red_add_v4(g_pool + (((long long)g * F4_TOT + COFF + c) << 2), a.x, a.y, a.z, a.w);
}

__global__ void k_pooldiv(float* __restrict__ out_graph) {
    int tid = blockIdx.x * blockDim.x + threadIdx.x;
    if (tid >= N_GRAPHS * F4_TOT) return;
    int g = tid / F4_TOT;
    float inv = 1.0f / fmaxf(g_cnt[g], 1.0f);
    float4 v = ((float4*)g_pool)[tid];
    v.x *= inv; v.y *= inv; v.z *= inv; v.w *= inv;
    ((float4*)out_graph)[tid] = v;
}

// ---------------------------------------------------------------------------
// Launch
// ---------------------------------------------------------------------------
extern "C" void kernel_launch(void* const* d_in, const int* in_sizes, int n_in,
                              void* d_out, int out_size) {
    const float* x     = (const float*)d_in[0];
    const void*  ei    = d_in[1];
    const void*  batch = d_in[2];
    const float *W1, *b1, *W2, *b2;
    if (n_in >= 8) {            // num_graphs passed as scalar input at slot 3
        W1 = (const float*)d_in[4]; b1 = (const float*)d_in[5];
        W2 = (const float*)d_in[6]; b2 = (const float*)d_in[7];
    } else {                    // num_graphs dropped
        W1 = (const float*)d_in[3]; b1 = (const float*)d_in[4];
        W2 = (const float*)d_in[5]; b2 = (const float*)d_in[6];
    }
    float* out       = (float*)d_out;
    float* out_graph = out;                      // [G, 384]
    float* out_node  = out + (size_t)N_GRAPHS * F_TOT;  // [N, 384]

    void *p_h, *p_h1, *p_agg2;
    cudaGetSymbolAddress(&p_h,    g_h);
    cudaGetSymbolAddress(&p_h1,   g_h1);
    cudaGetSymbolAddress(&p_agg2, g_agg2);
    float* h    = (float*)p_h;
    float* h1   = (float*)p_h1;
    float* agg2 = (float*)p_agg2;

    const int T = 256;
    k_detect<<<1, 32>>>(ei);
    k_zero<<<(N_GRAPHS * F_TOT + T - 1) / T, T>>>();
    k_deg<<<(N_EDGES + T - 1) / T, T>>>(ei);
    k_dinv<<<(N_NODES + T - 1) / T, T>>>();
    k_cnt<<<(N_NODES + T - 1) / T, T>>>(batch);

    // ---- Layer 1 ----
    k_sgemm<<<dim3(HID / 128, (N_NODES + 127) / 128), 256>>>(x, W1, h, N_NODES, HID, IN_C);
    {
        int total = N_NODES << 6;                 // F4 = 64
        k_selfloop<6><<<(total + T - 1) / T, T>>>(h, h1);
    }
    {
        long long total = (long long)N_EDGES << 6;
        k_scatter<6><<<(unsigned)((total + T - 1) / T), T>>>(h, h1, ei);
    }
    {
        int total = N_NODES << 6;
        k_finalize<6, 0, true><<<(total + T - 1) / T, T>>>(h1, b1, batch, out_node);
    }

    // ---- Layer 2 ----  (h buffer reused for h2pre = h1 @ W2)
    k_sgemm<<<dim3(OUT_C / 128, (N_NODES + 127) / 128), 256>>>(h1, W2, h, N_NODES, OUT_C, HID);
    {
        int total = N_NODES << 5;                 // F4 = 32
        k_selfloop<5><<<(total + T - 1) / T, T>>>(h, agg2);
    }
    {
        long long total = (long long)N_EDGES << 5;
        k_scatter<5><<<(unsigned)((total + T - 1) / T), T>>>(h, agg2, ei);
    }
    {
        int total = N_NODES << 5;
        k_finalize<5, 64, false><<<(total + T - 1) / T, T>>>(agg2, b2, batch, out_node);
    }

    // ---- Pool means ----
    k_pooldiv<<<(N_GRAPHS * F4_TOT + T - 1) / T, T>>>(out_graph);
}

// round 7
// speedup vs baseline: 2.3776x; 2.3776x over previous
#include <cuda_runtime.h>
#include <cuda_bf16.h>
#include <cstdint>

// Problem constants (fixed by the dataset)
#define N_NODES  50000
#define N_EDGES  800000
#define IN_C     768
#define HID      256
#define OUT_C    128
#define N_GRAPHS 256
#define F_TOT    384            // HID + OUT_C
#define F4_TOT   96             // F_TOT/4

// ---------------------------------------------------------------------------
// Scratch (device globals -- no runtime allocation allowed)
// ---------------------------------------------------------------------------
__device__ float g_h   [N_NODES * HID];    // pre-agg h = x@W1 ; reused as h2pre
__device__ float g_h1  [N_NODES * HID];    // layer1 output h1 (post relu)
__device__ float g_agg2[N_NODES * OUT_C];  // layer2 agg
__device__ float g_deg [N_NODES];
__device__ float g_dinv[N_NODES];
__device__ float g_pool[N_GRAPHS * F_TOT];
__device__ float g_cnt [N_GRAPHS];
__device__ int   g_idx64;

// bf16 split weights, [N][K] (k-contiguous -> matches mma .col B operand)
__device__ __nv_bfloat16 g_B1h[HID * IN_C];
__device__ __nv_bfloat16 g_B1l[HID * IN_C];
__device__ __nv_bfloat16 g_B2h[OUT_C * HID];
__device__ __nv_bfloat16 g_B2l[OUT_C * HID];

// ---------------------------------------------------------------------------
// Helpers
// ---------------------------------------------------------------------------
__device__ __forceinline__ uint32_t smem_to_u32(const void* p) {
    uint32_t a;
    asm("{ .reg .u64 t; cvta.to.shared.u64 t, %1; cvt.u32.u64 %0, t; }"
        : "=r"(a) : "l"(p));
    return a;
}

__device__ __forceinline__ void ldsm_x4(uint32_t* r, uint32_t addr) {
    asm volatile("ldmatrix.sync.aligned.m8n8.x4.shared.b16 {%0,%1,%2,%3}, [%4];"
                 : "=r"(r[0]), "=r"(r[1]), "=r"(r[2]), "=r"(r[3]) : "r"(addr));
}
__device__ __forceinline__ void ldsm_x2(uint32_t* r, uint32_t addr) {
    asm volatile("ldmatrix.sync.aligned.m8n8.x2.shared.b16 {%0,%1}, [%2];"
                 : "=r"(r[0]), "=r"(r[1]) : "r"(addr));
}

// D(f32) += A(bf16) * B(bf16) -- m16n8k16, A row-major, B col-major
__device__ __forceinline__ void mma_bf16(float* d, const uint32_t* a, const uint32_t* b) {
    asm volatile("mma.sync.aligned.m16n8k16.row.col.f32.bf16.bf16.f32 "
                 "{%0,%1,%2,%3}, {%4,%5,%6,%7}, {%8,%9}, {%0,%1,%2,%3};"
                 : "+f"(d[0]), "+f"(d[1]), "+f"(d[2]), "+f"(d[3])
                 : "r"(a[0]), "r"(a[1]), "r"(a[2]), "r"(a[3]),
                   "r"(b[0]), "r"(b[1]));
}

// bf16 split: x = hi + lo + O(2^-18 |x|)
__device__ __forceinline__ void bf16_split(float x, unsigned short& hi, unsigned short& lo) {
    __nv_bfloat16 h = __float2bfloat16(x);
    float r = x - __bfloat162float(h);
    __nv_bfloat16 l = __float2bfloat16(r);
    hi = __bfloat16_as_ushort(h);
    lo = __bfloat16_as_ushort(l);
}

__device__ __forceinline__ int load_idx(const void* p, long long i) {
    if (g_idx64) return (int)((const long long*)p)[i];
    return ((const int*)p)[i];
}
__device__ __forceinline__ void red_add_v4(float* p, float x, float y, float z, float w) {
    asm volatile("red.global.add.v4.f32 [%0], {%1,%2,%3,%4};"
                 :: "l"(p), "f"(x), "f"(y), "f"(z), "f"(w) : "memory");
}

// ---------------------------------------------------------------------------
// Prolog kernels
// ---------------------------------------------------------------------------
__global__ void k_detect(const void* ei) {
    if (threadIdx.x == 0 && blockIdx.x == 0) {
        const long long* p = (const long long*)ei;
        int ok = 1;
        for (int i = 0; i < 256; i++) {
            long long v = p[i];
            if (v < 0 || v >= N_NODES) { ok = 0; break; }
        }
        g_idx64 = ok;
    }
}

__global__ void k_zero() {
    int i = blockIdx.x * blockDim.x + threadIdx.x;
    if (i < N_NODES) g_deg[i] = 0.f;
    if (i < N_GRAPHS * F_TOT) g_pool[i] = 0.f;
    if (i < N_GRAPHS) g_cnt[i] = 0.f;
}

// Split + transpose W1, W2 into bf16 hi/lo [N][K]
__global__ void k_splitW(const float* __restrict__ W1, const float* __restrict__ W2) {
    int i = blockIdx.x * blockDim.x + threadIdx.x;
    if (i < IN_C * HID) {
        int k = i / HID, n = i % HID;
        unsigned short hi, lo;
        bf16_split(W1[i], hi, lo);
        g_B1h[n * IN_C + k] = __ushort_as_bfloat16(hi);
        g_B1l[n * IN_C + k] = __ushort_as_bfloat16(lo);
    } else {
        int j = i - IN_C * HID;
        if (j < HID * OUT_C) {
            int k = j / OUT_C, n = j % OUT_C;
            unsigned short hi, lo;
            bf16_split(W2[j], hi, lo);
            g_B2h[n * HID + k] = __ushort_as_bfloat16(hi);
            g_B2l[n * HID + k] = __ushort_as_bfloat16(lo);
        }
    }
}

__global__ void k_deg(const void* __restrict__ ei) {
    int e = blockIdx.x * blockDim.x + threadIdx.x;
    if (e < N_EDGES) {
        int d = load_idx(ei, (long long)N_EDGES + e);
        atomicAdd(&g_deg[d], 1.0f);
    }
}
__global__ void k_dinv() {
    int i = blockIdx.x * blockDim.x + threadIdx.x;
    if (i < N_NODES) g_dinv[i] = rsqrtf(g_deg[i] + 1.0f);
}
__global__ void k_cnt(const void* __restrict__ batch) {
    int i = blockIdx.x * blockDim.x + threadIdx.x;
    if (i < N_NODES) {
        int g = load_idx(batch, i);
        atomicAdd(&g_cnt[g], 1.0f);
    }
}

// ---------------------------------------------------------------------------
// mma.sync bf16-split GEMM: C[M,Nld] = A_fp32[M,K] @ B^T, B pre-split [N][K].
// Tile 128x128, BK=32, 256 threads (8 warps, 2x4 grid of 64x32 warp tiles).
// 3-term split: C = Ah*Bh + Ah*Bl + Al*Bh.
// smem pitch 80B per 32-elem bf16 row -> LDSM conflict-free.
// ---------------------------------------------------------------------------
#define PITCH 80
__global__ void __launch_bounds__(256, 2)
k_gemm_mma(const float* __restrict__ A,
           const __nv_bfloat16* __restrict__ Bh,
           const __nv_bfloat16* __restrict__ Bl,
           float* __restrict__ C, int M, int Nld, int K) {
    __shared__ __align__(16) char sAh[128 * PITCH];
    __shared__ __align__(16) char sAl[128 * PITCH];
    __shared__ __align__(16) char sBh[128 * PITCH];
    __shared__ __align__(16) char sBl[128 * PITCH];

    const int tid  = threadIdx.x;
    const int lane = tid & 31;
    const int wid  = tid >> 5;
    const int wm   = (wid & 1) * 64;   // warp row offset in tile
    const int wn   = (wid >> 1) * 32;  // warp col offset in tile
    const int mBase = blockIdx.y * 128;
    const int nBase = blockIdx.x * 128;

    const uint32_t uAh = smem_to_u32(sAh);
    const uint32_t uAl = smem_to_u32(sAl);
    const uint32_t uBh = smem_to_u32(sBh);
    const uint32_t uBl = smem_to_u32(sBl);

    float acc[4][4][4];
#pragma unroll
    for (int i = 0; i < 4; i++)
#pragma unroll
        for (int j = 0; j < 4; j++)
#pragma unroll
            for (int q = 0; q < 4; q++) acc[i][j][q] = 0.f;

    // ldmatrix source addresses (byte offsets within a tile)
    const int aRow = lane & 15;              // A: row within 16-row frag
    const int aK   = (lane >> 4) * 16;       // A: 8-bf16 col segment (bytes)
    const int l16  = lane & 15;
    const int bRow = l16 & 7;                // B: row within 8-row frag
    const int bK   = (l16 >> 3) * 16;        // B: k segment (bytes)

    for (int k0 = 0; k0 < K; k0 += 32) {
        // --- stage A tile: 128 x 32 fp32 -> bf16 hi/lo ---
#pragma unroll
        for (int it = 0; it < 4; it++) {
            int idx = it * 256 + tid;        // 0..1023 float4s
            int m = idx >> 3, q = idx & 7;
            float4 v = make_float4(0.f, 0.f, 0.f, 0.f);
            int gm = mBase + m;
            if (gm < M) v = *(const float4*)(A + (size_t)gm * K + k0 + q * 4);
            unsigned short h0, l0, h1, l1, h2, l2, h3, l3;
            bf16_split(v.x, h0, l0); bf16_split(v.y, h1, l1);
            bf16_split(v.z, h2, l2); bf16_split(v.w, h3, l3);
            uint2 hw, lw;
            hw.x = ((uint32_t)h1 << 16) | h0;  hw.y = ((uint32_t)h3 << 16) | h2;
            lw.x = ((uint32_t)l1 << 16) | l0;  lw.y = ((uint32_t)l3 << 16) | l2;
            int off = m * PITCH + q * 8;
            *(uint2*)(sAh + off) = hw;
            *(uint2*)(sAl + off) = lw;
        }
        // --- stage B tiles: 128 x 32 bf16 hi & lo ---
#pragma unroll
        for (int it = 0; it < 2; it++) {
            int idx = it * 256 + tid;        // 0..511 uint4s
            int n = idx >> 2, q = idx & 3;
            size_t g = (size_t)(nBase + n) * K + k0 + q * 8;
            int off = n * PITCH + q * 16;
            *(uint4*)(sBh + off) = *(const uint4*)(Bh + g);
            *(uint4*)(sBl + off) = *(const uint4*)(Bl + g);
        }
        __syncthreads();

#pragma unroll
        for (int ks = 0; ks < 2; ks++) {
            const int koff = ks * 32;        // 16 bf16 = 32 bytes
            uint32_t bhf[4][2], blf[4][2];
#pragma unroll
            for (int nf = 0; nf < 4; nf++) {
                uint32_t ro = (uint32_t)(wn + nf * 8 + bRow) * PITCH + koff + bK;
                ldsm_x2(bhf[nf], uBh + ro);
                ldsm_x2(blf[nf], uBl + ro);
            }
#pragma unroll
            for (int mf = 0; mf < 4; mf++) {
                uint32_t ah[4], al[4];
                uint32_t ro = (uint32_t)(wm + mf * 16 + aRow) * PITCH + koff + aK;
                ldsm_x4(ah, uAh + ro);
                ldsm_x4(al, uAl + ro);
#pragma unroll
                for (int nf = 0; nf < 4; nf++) {
                    mma_bf16(acc[mf][nf], ah, bhf[nf]);
                    mma_bf16(acc[mf][nf], ah, blf[nf]);
                    mma_bf16(acc[mf][nf], al, bhf[nf]);
                }
            }
        }
        __syncthreads();
    }

    // --- epilogue: D fragment rows = lane/4 (+8), cols = (lane%4)*2 ---
#pragma unroll
    for (int mf = 0; mf < 4; mf++) {
        int r0 = mBase + wm + mf * 16 + (lane >> 2);
#pragma unroll
        for (int nf = 0; nf < 4; nf++) {
            int c0 = nBase + wn + nf * 8 + (lane & 3) * 2;
            if (r0 < M)
                *(float2*)(C + (size_t)r0 * Nld + c0) =
                    make_float2(acc[mf][nf][0], acc[mf][nf][1]);
            if (r0 + 8 < M)
                *(float2*)(C + (size_t)(r0 + 8) * Nld + c0) =
                    make_float2(acc[mf][nf][2], acc[mf][nf][3]);
        }
    }
}

// ---------------------------------------------------------------------------
// agg[i] = h[i] * dinv[i]^2  (self-loop term)
// ---------------------------------------------------------------------------
template <int SH>
__global__ void k_selfloop(const float* __restrict__ h, float* __restrict__ agg) {
    int tid = blockIdx.x * blockDim.x + threadIdx.x;
    if (tid >= (N_NODES << SH)) return;
    int i = tid >> SH;
    float di = g_dinv[i];
    float s = di * di;
    float4 v = ((const float4*)h)[tid];
    v.x *= s; v.y *= s; v.z *= s; v.w *= s;
    ((float4*)agg)[tid] = v;
}

// ---------------------------------------------------------------------------
// Edge scatter: agg[dst] += h[src] * dinv[src]*dinv[dst]
// ---------------------------------------------------------------------------
template <int SH>
__global__ void __launch_bounds__(256)
k_scatter(const float* __restrict__ h, float* __restrict__ agg,
          const void* __restrict__ ei) {
    long long tid = (long long)blockIdx.x * blockDim.x + threadIdx.x;
    long long e = tid >> SH;
    if (e >= N_EDGES) return;
    int c = (int)(tid & ((1 << SH) - 1));
    int s = load_idx(ei, e);
    int d = load_idx(ei, (long long)N_EDGES + e);
    float nrm = g_dinv[s] * g_dinv[d];
    float4 v = ((const float4*)h)[((long long)s << SH) + c];
    float* dstp = agg + ((((long long)d << SH) + c) << 2);
    red_add_v4(dstp, v.x * nrm, v.y * nrm, v.z * nrm, v.w * nrm);
}

// ---------------------------------------------------------------------------
// Finalize: h = relu(agg + bias); write node_embed slice; red into pool sums.
// ---------------------------------------------------------------------------
template <int SH, int COFF, bool STORE_BACK>
__global__ void k_finalize(float* __restrict__ agg, const float* __restrict__ bias,
                           const void* __restrict__ batch, float* __restrict__ out_node) {
    int tid = blockIdx.x * blockDim.x + threadIdx.x;
    if (tid >= (N_NODES << SH)) return;
    int i = tid >> SH;
    int c = tid & ((1 << SH) - 1);
    float4 a  = ((float4*)agg)[tid];
    float4 bb = ((const float4*)bias)[c];
    a.x = fmaxf(a.x + bb.x, 0.f);
    a.y = fmaxf(a.y + bb.y, 0.f);
    a.z = fmaxf(a.z + bb.z, 0.f);
    a.w = fmaxf(a.w + bb.w, 0.f);
    if (STORE_BACK) ((float4*)agg)[tid] = a;
    ((float4*)out_node)[(long long)i * F4_TOT + COFF + c] = a;
    int g = load_idx(batch, i);
    red_add_v4(g_pool + (((long long)g * F4_TOT + COFF + c) << 2), a.x, a.y, a.z, a.w);
}

__global__ void k_pooldiv(float* __restrict__ out_graph) {
    int tid = blockIdx.x * blockDim.x + threadIdx.x;
    if (tid >= N_GRAPHS * F4_TOT) return;
    int g = tid / F4_TOT;
    float inv = 1.0f / fmaxf(g_cnt[g], 1.0f);
    float4 v = ((float4*)g_pool)[tid];
    v.x *= inv; v.y *= inv; v.z *= inv; v.w *= inv;
    ((float4*)out_graph)[tid] = v;
}

// ---------------------------------------------------------------------------
// Launch
// ---------------------------------------------------------------------------
extern "C" void kernel_launch(void* const* d_in, const int* in_sizes, int n_in,
                              void* d_out, int out_size) {
    const float* x     = (const float*)d_in[0];
    const void*  ei    = d_in[1];
    const void*  batch = d_in[2];
    const float *W1, *b1, *W2, *b2;
    if (n_in >= 8) {
        W1 = (const float*)d_in[4]; b1 = (const float*)d_in[5];
        W2 = (const float*)d_in[6]; b2 = (const float*)d_in[7];
    } else {
        W1 = (const float*)d_in[3]; b1 = (const float*)d_in[4];
        W2 = (const float*)d_in[5]; b2 = (const float*)d_in[6];
    }
    float* out       = (float*)d_out;
    float* out_graph = out;
    float* out_node  = out + (size_t)N_GRAPHS * F_TOT;

    void *p_h, *p_h1, *p_agg2, *p_B1h, *p_B1l, *p_B2h, *p_B2l;
    cudaGetSymbolAddress(&p_h,    g_h);
    cudaGetSymbolAddress(&p_h1,   g_h1);
    cudaGetSymbolAddress(&p_agg2, g_agg2);
    cudaGetSymbolAddress(&p_B1h,  g_B1h);
    cudaGetSymbolAddress(&p_B1l,  g_B1l);
    cudaGetSymbolAddress(&p_B2h,  g_B2h);
    cudaGetSymbolAddress(&p_B2l,  g_B2l);
    float* h    = (float*)p_h;
    float* h1   = (float*)p_h1;
    float* agg2 = (float*)p_agg2;

    const int T = 256;
    k_detect<<<1, 32>>>(ei);
    k_zero<<<(N_GRAPHS * F_TOT + T - 1) / T, T>>>();
    k_splitW<<<(IN_C * HID + HID * OUT_C + T - 1) / T, T>>>(W1, W2);

    // ---- Layer 1 GEMM: h = x @ W1 ----
    k_gemm_mma<<<dim3(HID / 128, (N_NODES + 127) / 128), 256>>>(
        x, (const __nv_bfloat16*)p_B1h, (const __nv_bfloat16*)p_B1l,
        h, N_NODES, HID, IN_C);

    k_deg<<<(N_EDGES + T - 1) / T, T>>>(ei);
    k_dinv<<<(N_NODES + T - 1) / T, T>>>();
    k_cnt<<<(N_NODES + T - 1) / T, T>>>(batch);

    // ---- Layer 1 aggregate ----
    {
        int total = N_NODES << 6;                 // F4 = 64
        k_selfloop<6><<<(total + T - 1) / T, T>>>(h, h1);
    }
    {
        long long total = (long long)N_EDGES << 6;
        k_scatter<6><<<(unsigned)((total + T - 1) / T), T>>>(h, h1, ei);
    }
    {
        int total = N_NODES << 6;
        k_finalize<6, 0, true><<<(total + T - 1) / T, T>>>(h1, b1, batch, out_node);
    }

    // ---- Layer 2 GEMM: h2pre = h1 @ W2 (reuses h buffer) ----
    k_gemm_mma<<<dim3(OUT_C / 128, (N_NODES + 127) / 128), 256>>>(
        h1, (const __nv_bfloat16*)p_B2h, (const __nv_bfloat16*)p_B2l,
        h, N_NODES, OUT_C, HID);

    // ---- Layer 2 aggregate ----
    {
        int total = N_NODES << 5;                 // F4 = 32
        k_selfloop<5><<<(total + T - 1) / T, T>>>(h, agg2);
    }
    {
        long long total = (long long)N_EDGES << 5;
        k_scatter<5><<<(unsigned)((total + T - 1) / T), T>>>(h, agg2, ei);
    }
    {
        int total = N_NODES << 5;
        k_finalize<5, 64, false><<<(total + T - 1) / T, T>>>(agg2, b2, batch, out_node);
    }

    // ---- Pool means ----
    k_pooldiv<<<(N_GRAPHS * F4_TOT + T - 1) / T, T>>>(out_graph);
}

// round 8
// speedup vs baseline: 3.3538x; 1.4105x over previous
#include <cuda_runtime.h>
#include <cuda_bf16.h>
#include <cstdint>

// Problem constants (fixed by the dataset)
#define N_NODES  50000
#define N_EDGES  800000
#define IN_C     768
#define HID      256
#define OUT_C    128
#define N_GRAPHS 256
#define F_TOT    384
#define F4_TOT   96

// ---------------------------------------------------------------------------
// Scratch (device globals)
// ---------------------------------------------------------------------------
__device__ float g_h   [N_NODES * HID];     // GEMM output (pre-agg), reused both layers
__device__ float g_deg [N_NODES];
__device__ float g_dinv[N_NODES];
__device__ float g_pool[N_GRAPHS * F_TOT];
__device__ float g_cnt [N_GRAPHS];
__device__ int   g_idx64;

// CSR
__device__ int   g_off   [N_NODES + 1];
__device__ int   g_cursor[N_NODES];
__device__ int   g_csr   [N_EDGES];
__device__ float g_csrw  [N_EDGES];

// bf16 split operands
__device__ __nv_bfloat16 g_Ah[N_NODES * IN_C];   // A hi (x for L1, h1 for L2)
__device__ __nv_bfloat16 g_Al[N_NODES * IN_C];   // A lo
__device__ __nv_bfloat16 g_B1h[HID * IN_C];
__device__ __nv_bfloat16 g_B1l[HID * IN_C];
__device__ __nv_bfloat16 g_B2h[OUT_C * HID];
__device__ __nv_bfloat16 g_B2l[OUT_C * HID];

// ---------------------------------------------------------------------------
// Helpers
// ---------------------------------------------------------------------------
__device__ __forceinline__ uint32_t smem_to_u32(const void* p) {
    uint32_t a;
    asm("{ .reg .u64 t; cvta.to.shared.u64 t, %1; cvt.u32.u64 %0, t; }"
        : "=r"(a) : "l"(p));
    return a;
}
__device__ __forceinline__ void ldsm_x4(uint32_t* r, uint32_t addr) {
    asm volatile("ldmatrix.sync.aligned.m8n8.x4.shared.b16 {%0,%1,%2,%3}, [%4];"
                 : "=r"(r[0]), "=r"(r[1]), "=r"(r[2]), "=r"(r[3]) : "r"(addr));
}
__device__ __forceinline__ void ldsm_x2(uint32_t* r, uint32_t addr) {
    asm volatile("ldmatrix.sync.aligned.m8n8.x2.shared.b16 {%0,%1}, [%2];"
                 : "=r"(r[0]), "=r"(r[1]) : "r"(addr));
}
__device__ __forceinline__ void mma_bf16(float* d, const uint32_t* a, const uint32_t* b) {
    asm volatile("mma.sync.aligned.m16n8k16.row.col.f32.bf16.bf16.f32 "
                 "{%0,%1,%2,%3}, {%4,%5,%6,%7}, {%8,%9}, {%0,%1,%2,%3};"
                 : "+f"(d[0]), "+f"(d[1]), "+f"(d[2]), "+f"(d[3])
                 : "r"(a[0]), "r"(a[1]), "r"(a[2]), "r"(a[3]),
                   "r"(b[0]), "r"(b[1]));
}
__device__ __forceinline__ void cp16(uint32_t dst, const void* src, int bytes) {
    asm volatile("cp.async.ca.shared.global [%0], [%1], 16, %2;"
                 :: "r"(dst), "l"(src), "r"(bytes) : "memory");
}
#define CP_COMMIT() asm volatile("cp.async.commit_group;" ::: "memory")
template <int NG> __device__ __forceinline__ void cp_wait() {
    asm volatile("cp.async.wait_group %0;" :: "n"(NG) : "memory");
}

__device__ __forceinline__ void bf16_split(float x, unsigned short& hi, unsigned short& lo) {
    __nv_bfloat16 h = __float2bfloat16(x);
    float r = x - __bfloat162float(h);
    __nv_bfloat16 l = __float2bfloat16(r);
    hi = __bfloat16_as_ushort(h);
    lo = __bfloat16_as_ushort(l);
}
__device__ __forceinline__ int load_idx(const void* p, long long i) {
    if (g_idx64) return (int)((const long long*)p)[i];
    return ((const int*)p)[i];
}
__device__ __forceinline__ void red_add_v4(float* p, float x, float y, float z, float w) {
    asm volatile("red.global.add.v4.f32 [%0], {%1,%2,%3,%4};"
                 :: "l"(p), "f"(x), "f"(y), "f"(z), "f"(w) : "memory");
}

// ---------------------------------------------------------------------------
// Prolog kernels
// ---------------------------------------------------------------------------
__global__ void k_detect(const void* ei) {
    if (threadIdx.x == 0 && blockIdx.x == 0) {
        const long long* p = (const long long*)ei;
        int ok = 1;
        for (int i = 0; i < 256; i++) {
            long long v = p[i];
            if (v < 0 || v >= N_NODES) { ok = 0; break; }
        }
        g_idx64 = ok;
    }
}

__global__ void k_zero() {
    int i = blockIdx.x * blockDim.x + threadIdx.x;
    if (i < N_NODES) g_deg[i] = 0.f;
    if (i < N_GRAPHS * F_TOT) g_pool[i] = 0.f;
    if (i < N_GRAPHS) g_cnt[i] = 0.f;
}

__global__ void k_splitW(const float* __restrict__ W1, const float* __restrict__ W2) {
    int i = blockIdx.x * blockDim.x + threadIdx.x;
    if (i < IN_C * HID) {
        int k = i / HID, n = i % HID;
        unsigned short hi, lo;
        bf16_split(W1[i], hi, lo);
        g_B1h[n * IN_C + k] = __ushort_as_bfloat16(hi);
        g_B1l[n * IN_C + k] = __ushort_as_bfloat16(lo);
    } else {
        int j = i - IN_C * HID;
        if (j < HID * OUT_C) {
            int k = j / OUT_C, n = j % OUT_C;
            unsigned short hi, lo;
            bf16_split(W2[j], hi, lo);
            g_B2h[n * HID + k] = __ushort_as_bfloat16(hi);
            g_B2l[n * HID + k] = __ushort_as_bfloat16(lo);
        }
    }
}

// Elementwise split of A matrix fp32 -> bf16 hi/lo (vectorized float4)
__global__ void k_splitA(const float* __restrict__ A, int n4) {
    int i = blockIdx.x * blockDim.x + threadIdx.x;
    if (i >= n4) return;
    float4 v = ((const float4*)A)[i];
    unsigned short h0, l0, h1, l1, h2, l2, h3, l3;
    bf16_split(v.x, h0, l0); bf16_split(v.y, h1, l1);
    bf16_split(v.z, h2, l2); bf16_split(v.w, h3, l3);
    uint2 hw, lw;
    hw.x = ((uint32_t)h1 << 16) | h0;  hw.y = ((uint32_t)h3 << 16) | h2;
    lw.x = ((uint32_t)l1 << 16) | l0;  lw.y = ((uint32_t)l3 << 16) | l2;
    ((uint2*)g_Ah)[i] = hw;
    ((uint2*)g_Al)[i] = lw;
}

__global__ void k_deg(const void* __restrict__ ei) {
    int e = blockIdx.x * blockDim.x + threadIdx.x;
    if (e < N_EDGES) {
        int d = load_idx(ei, (long long)N_EDGES + e);
        atomicAdd(&g_deg[d], 1.0f);
    }
}
__global__ void k_dinv() {
    int i = blockIdx.x * blockDim.x + threadIdx.x;
    if (i < N_NODES) g_dinv[i] = rsqrtf(g_deg[i] + 1.0f);
}
__global__ void k_cnt(const void* __restrict__ batch) {
    int i = blockIdx.x * blockDim.x + threadIdx.x;
    if (i < N_NODES) {
        int g = load_idx(batch, i);
        atomicAdd(&g_cnt[g], 1.0f);
    }
}

// Exclusive scan of deg -> g_off / g_cursor. Single block, 1024 threads.
__global__ void k_scan() {
    __shared__ int swarp[32];
    __shared__ int s_carry;
    int tid = threadIdx.x, lane = tid & 31, wid = tid >> 5;
    if (tid == 0) s_carry = 0;
    __syncthreads();
    for (int base = 0; base < N_NODES; base += 1024) {
        int i = base + tid;
        int v = (i < N_NODES) ? (int)g_deg[i] : 0;
        int incl = v;
#pragma unroll
        for (int o = 1; o < 32; o <<= 1) {
            int t = __shfl_up_sync(0xFFFFFFFFu, incl, o);
            if (lane >= o) incl += t;
        }
        if (lane == 31) swarp[wid] = incl;
        __syncthreads();
        if (wid == 0) {
            int ws = swarp[lane];
            int wincl = ws;
#pragma unroll
            for (int o = 1; o < 32; o <<= 1) {
                int t = __shfl_up_sync(0xFFFFFFFFu, wincl, o);
                if (lane >= o) wincl += t;
            }
            swarp[lane] = wincl - ws;   // exclusive warp offsets
        }
        __syncthreads();
        int ex = s_carry + swarp[wid] + incl - v;
        if (i < N_NODES) { g_off[i] = ex; g_cursor[i] = ex; }
        __syncthreads();
        if (tid == 1023) s_carry = ex + v;
        __syncthreads();
    }
    if (threadIdx.x == 0) g_off[N_NODES] = s_carry;
}

// Fill CSR: slot via cursor atomics; precompute edge weight.
__global__ void k_fill(const void* __restrict__ ei) {
    int e = blockIdx.x * blockDim.x + threadIdx.x;
    if (e >= N_EDGES) return;
    int s = load_idx(ei, e);
    int d = load_idx(ei, (long long)N_EDGES + e);
    int p = atomicAdd(&g_cursor[d], 1);
    g_csr[p]  = s;
    g_csrw[p] = g_dinv[s] * g_dinv[d];
}

// ---------------------------------------------------------------------------
// Pipelined bf16-split GEMM: C[M,Nld] = A @ B^T (A/B pre-split bf16 hi/lo,
// A row-major [M,K], B [N,K]). Tile 128x128, BK=32, cp.async double buffer.
// smem: 2 buffers x (Ah|Al|Bh|Bl) x 128*PITCH.
// ---------------------------------------------------------------------------
#define PITCH    80
#define TILE_B   (128 * PITCH)        // 10240
#define STAGE_B  (4 * TILE_B)         // 40960
__global__ void __launch_bounds__(256, 2)
k_gemm(const __nv_bfloat16* __restrict__ Ah, const __nv_bfloat16* __restrict__ Al,
       const __nv_bfloat16* __restrict__ Bh, const __nv_bfloat16* __restrict__ Bl,
       float* __restrict__ C, int M, int Nld, int K) {
    extern __shared__ char smem[];
    const int tid  = threadIdx.x;
    const int lane = tid & 31;
    const int wid  = tid >> 5;
    const int wm   = (wid & 1) * 64;
    const int wn   = (wid >> 1) * 32;
    const int mBase = blockIdx.y * 128;
    const int nBase = blockIdx.x * 128;
    const uint32_t sbase = smem_to_u32(smem);

    float acc[4][4][4];
#pragma unroll
    for (int i = 0; i < 4; i++)
#pragma unroll
        for (int j = 0; j < 4; j++)
#pragma unroll
            for (int q = 0; q < 4; q++) acc[i][j][q] = 0.f;

    const int aRow = lane & 15;
    const int aK   = (lane >> 4) * 16;
    const int bRow = lane & 7;
    const int bK   = ((lane & 15) >> 3) * 16;

    const int nch = K >> 5;

    // stage chunk ch into buffer buf (8 x cp.async 16B per thread)
    auto stage = [&](int ch, int buf) {
        const int k0 = ch << 5;
        const uint32_t sb = sbase + buf * STAGE_B;
#pragma unroll
        for (int t = 0; t < 2; t++) {
            int idx = t * 256 + tid;          // 0..511
            int m = idx >> 2, q = idx & 3;
            uint32_t so = sb + m * PITCH + q * 16;
            int gm = mBase + m;
            int okA = (gm < M) ? 16 : 0;
            if (!okA) gm = 0;
            const size_t ga = (size_t)gm * K + k0 + q * 8;
            cp16(so,              Ah + ga, okA);
            cp16(so + TILE_B,     Al + ga, okA);
            const size_t gb = (size_t)(nBase + m) * K + k0 + q * 8;
            cp16(so + 2 * TILE_B, Bh + gb, 16);
            cp16(so + 3 * TILE_B, Bl + gb, 16);
        }
    };

    stage(0, 0); CP_COMMIT();
    for (int ch = 0; ch < nch; ch++) {
        const int buf = ch & 1;
        if (ch + 1 < nch) { stage(ch + 1, buf ^ 1); CP_COMMIT(); cp_wait<1>(); }
        else              { cp_wait<0>(); }
        __syncthreads();
        const uint32_t sb = sbase + buf * STAGE_B;
#pragma unroll
        for (int ks = 0; ks < 2; ks++) {
            const int koff = ks * 32;
            uint32_t bhf[4][2], blf[4][2];
#pragma unroll
            for (int nf = 0; nf < 4; nf++) {
                uint32_t ro = sb + 2 * TILE_B + (uint32_t)(wn + nf * 8 + bRow) * PITCH + koff + bK;
                ldsm_x2(bhf[nf], ro);
                ldsm_x2(blf[nf], ro + TILE_B);
            }
#pragma unroll
            for (int mf = 0; mf < 4; mf++) {
                uint32_t ah[4], al[4];
                uint32_t ro = sb + (uint32_t)(wm + mf * 16 + aRow) * PITCH + koff + aK;
                ldsm_x4(ah, ro);
                ldsm_x4(al, ro + TILE_B);
#pragma unroll
                for (int nf = 0; nf < 4; nf++) {
                    mma_bf16(acc[mf][nf], ah, bhf[nf]);
                    mma_bf16(acc[mf][nf], ah, blf[nf]);
                    mma_bf16(acc[mf][nf], al, bhf[nf]);
                }
            }
        }
        __syncthreads();
    }

#pragma unroll
    for (int mf = 0; mf < 4; mf++) {
        int r0 = mBase + wm + mf * 16 + (lane >> 2);
#pragma unroll
        for (int nf = 0; nf < 4; nf++) {
            int c0 = nBase + wn + nf * 8 + (lane & 3) * 2;
            if (r0 < M)
                *(float2*)(C + (size_t)r0 * Nld + c0) =
                    make_float2(acc[mf][nf][0], acc[mf][nf][1]);
            if (r0 + 8 < M)
                *(float2*)(C + (size_t)(r0 + 8) * Nld + c0) =
                    make_float2(acc[mf][nf][2], acc[mf][nf][3]);
        }
    }
}

// ---------------------------------------------------------------------------
// Fused CSR aggregation: warp per node.
//   acc = h[i]*dinv[i]^2 + sum_in-edges h[src]*w ; a = relu(acc + bias)
//   -> out_node slice, pool red, and (if SPLIT_OUT) bf16 hi/lo of a into g_Ah/g_Al.
// SH: log2(float4 per row) = 6 (256 feat) or 5 (128 feat). C = chunks per lane.
// ---------------------------------------------------------------------------
template <int SH, int COFF, bool SPLIT_OUT>
__global__ void __launch_bounds__(256)
k_agg(const float* __restrict__ h, const float* __restrict__ bias,
      const void* __restrict__ batch, float* __restrict__ out_node) {
    const int gw   = (blockIdx.x * blockDim.x + threadIdx.x) >> 5;
    const int lane = threadIdx.x & 31;
    if (gw >= N_NODES) return;
    const int i = gw;
    constexpr int C = 1 << (SH - 5);
    const float4* h4 = (const float4*)h;

    float4 acc[C];
    const float di = g_dinv[i];
    const float s2 = di * di;
#pragma unroll
    for (int c = 0; c < C; c++) {
        float4 v = h4[((size_t)i << SH) + lane + c * 32];
        acc[c] = make_float4(v.x * s2, v.y * s2, v.z * s2, v.w * s2);
    }

    int j  = g_off[i];
    const int je = g_off[i + 1];
    for (; j + 1 < je; j += 2) {
        int   s0 = g_csr[j],     s1 = g_csr[j + 1];
        float w0 = g_csrw[j],    w1 = g_csrw[j + 1];
        float4 v0[C], v1[C];
#pragma unroll
        for (int c = 0; c < C; c++) {
            v0[c] = h4[((size_t)s0 << SH) + lane + c * 32];
            v1[c] = h4[((size_t)s1 << SH) + lane + c * 32];
        }
#pragma unroll
        for (int c = 0; c < C; c++) {
            acc[c].x += v0[c].x * w0 + v1[c].x * w1;
            acc[c].y += v0[c].y * w0 + v1[c].y * w1;
            acc[c].z += v0[c].z * w0 + v1[c].z * w1;
            acc[c].w += v0[c].w * w0 + v1[c].w * w1;
        }
    }
    if (j < je) {
        int   s0 = g_csr[j];
        float w0 = g_csrw[j];
#pragma unroll
        for (int c = 0; c < C; c++) {
            float4 v = h4[((size_t)s0 << SH) + lane + c * 32];
            acc[c].x += v.x * w0; acc[c].y += v.y * w0;
            acc[c].z += v.z * w0; acc[c].w += v.w * w0;
        }
    }

    const int g = load_idx(batch, i);
    const float4* bias4 = (const float4*)bias;
#pragma unroll
    for (int c = 0; c < C; c++) {
        float4 bb = bias4[lane + c * 32];
        float4 a;
        a.x = fmaxf(acc[c].x + bb.x, 0.f);
        a.y = fmaxf(acc[c].y + bb.y, 0.f);
        a.z = fmaxf(acc[c].z + bb.z, 0.f);
        a.w = fmaxf(acc[c].w + bb.w, 0.f);
        ((float4*)out_node)[(size_t)i * F4_TOT + COFF + lane + c * 32] = a;
        red_add_v4(g_pool + (((size_t)g * F4_TOT + COFF + lane + c * 32) << 2),
                   a.x, a.y, a.z, a.w);
        if (SPLIT_OUT) {
            unsigned short h0, l0, h1, l1, h2, l2, h3, l3;
            bf16_split(a.x, h0, l0); bf16_split(a.y, h1, l1);
            bf16_split(a.z, h2, l2); bf16_split(a.w, h3, l3);
            uint2 hw, lw;
            hw.x = ((uint32_t)h1 << 16) | h0;  hw.y = ((uint32_t)h3 << 16) | h2;
            lw.x = ((uint32_t)l1 << 16) | l0;  lw.y = ((uint32_t)l3 << 16) | l2;
            size_t o = ((size_t)i << SH) + lane + c * 32;
            ((uint2*)g_Ah)[o] = hw;
            ((uint2*)g_Al)[o] = lw;
        }
    }
}

__global__ void k_pooldiv(float* __restrict__ out_graph) {
    int tid = blockIdx.x * blockDim.x + threadIdx.x;
    if (tid >= N_GRAPHS * F4_TOT) return;
    int g = tid / F4_TOT;
    float inv = 1.0f / fmaxf(g_cnt[g], 1.0f);
    float4 v = ((float4*)g_pool)[tid];
    v.x *= inv; v.y *= inv; v.z *= inv; v.w *= inv;
    ((float4*)out_graph)[tid] = v;
}

// ---------------------------------------------------------------------------
// Launch
// ---------------------------------------------------------------------------
extern "C" void kernel_launch(void* const* d_in, const int* in_sizes, int n_in,
                              void* d_out, int out_size) {
    const float* x     = (const float*)d_in[0];
    const void*  ei    = d_in[1];
    const void*  batch = d_in[2];
    const float *W1, *b1, *W2, *b2;
    if (n_in >= 8) {
        W1 = (const float*)d_in[4]; b1 = (const float*)d_in[5];
        W2 = (const float*)d_in[6]; b2 = (const float*)d_in[7];
    } else {
        W1 = (const float*)d_in[3]; b1 = (const float*)d_in[4];
        W2 = (const float*)d_in[5]; b2 = (const float*)d_in[6];
    }
    float* out       = (float*)d_out;
    float* out_graph = out;
    float* out_node  = out + (size_t)N_GRAPHS * F_TOT;

    void *p_h, *p_Ah, *p_Al, *p_B1h, *p_B1l, *p_B2h, *p_B2l;
    cudaGetSymbolAddress(&p_h,   g_h);
    cudaGetSymbolAddress(&p_Ah,  g_Ah);
    cudaGetSymbolAddress(&p_Al,  g_Al);
    cudaGetSymbolAddress(&p_B1h, g_B1h);
    cudaGetSymbolAddress(&p_B1l, g_B1l);
    cudaGetSymbolAddress(&p_B2h, g_B2h);
    cudaGetSymbolAddress(&p_B2l, g_B2l);
    float* h = (float*)p_h;

    cudaFuncSetAttribute(k_gemm, cudaFuncAttributeMaxDynamicSharedMemorySize, 2 * STAGE_B);

    const int T = 256;
    k_detect<<<1, 32>>>(ei);
    k_zero<<<(N_GRAPHS * F_TOT + T - 1) / T, T>>>();
    k_splitW<<<(IN_C * HID + HID * OUT_C + T - 1) / T, T>>>(W1, W2);
    k_splitA<<<(N_NODES * IN_C / 4 + T - 1) / T, T>>>(x, N_NODES * IN_C / 4);

    // ---- Layer 1 GEMM: h = x @ W1 ----
    k_gemm<<<dim3(HID / 128, (N_NODES + 127) / 128), 256, 2 * STAGE_B>>>(
        (const __nv_bfloat16*)p_Ah, (const __nv_bfloat16*)p_Al,
        (const __nv_bfloat16*)p_B1h, (const __nv_bfloat16*)p_B1l,
        h, N_NODES, HID, IN_C);

    // ---- CSR build (overlapped in-order after GEMM launch) ----
    k_deg<<<(N_EDGES + T - 1) / T, T>>>(ei);
    k_dinv<<<(N_NODES + T - 1) / T, T>>>();
    k_cnt<<<(N_NODES + T - 1) / T, T>>>(batch);
    k_scan<<<1, 1024>>>();
    k_fill<<<(N_EDGES + T - 1) / T, T>>>(ei);

    // ---- Layer 1 aggregate (fused: selfloop+gather+relu+bias+pool+split) ----
    k_agg<6, 0, true><<<(N_NODES * 32 + T - 1) / T, T>>>(h, b1, batch, out_node);

    // ---- Layer 2 GEMM: h2pre = h1 @ W2 (A = split h1 from agg epilogue) ----
    k_gemm<<<dim3(OUT_C / 128, (N_NODES + 127) / 128), 256, 2 * STAGE_B>>>(
        (const __nv_bfloat16*)p_Ah, (const __nv_bfloat16*)p_Al,
        (const __nv_bfloat16*)p_B2h, (const __nv_bfloat16*)p_B2l,
        h, N_NODES, OUT_C, HID);

    // ---- Layer 2 aggregate ----
    k_agg<5, 64, false><<<(N_NODES * 32 + T - 1) / T, T>>>(h, b2, batch, out_node);

    // ---- Pool means ----
    k_pooldiv<<<(N_GRAPHS * F4_TOT + T - 1) / T, T>>>(out_graph);
}

// round 9
// speedup vs baseline: 4.0281x; 1.2011x over previous
#include <cuda_runtime.h>
#include <cuda_bf16.h>
#include <cstdint>

// Problem constants (fixed by the dataset)
#define N_NODES  50000
#define N_EDGES  800000
#define IN_C     768
#define HID      256
#define OUT_C    128
#define N_GRAPHS 256
#define F_TOT    384
#define F4_TOT   96

// ---------------------------------------------------------------------------
// Scratch (device globals)
// ---------------------------------------------------------------------------
__device__ float g_h   [N_NODES * HID];     // GEMM output (pre-agg), reused both layers
__device__ float g_deg [N_NODES];
__device__ float g_dinv[N_NODES];
__device__ float g_pool[N_GRAPHS * F_TOT];
__device__ float g_cnt [N_GRAPHS];
__device__ int   g_idx64;

// CSR
__device__ int   g_off   [N_NODES + 1];
__device__ int   g_cursor[N_NODES];
__device__ int   g_csr   [N_EDGES];
__device__ float g_csrw  [N_EDGES];

// bf16 split A for layer-2 GEMM (filled by agg1 epilogue)
__device__ __nv_bfloat16 g_Ah[N_NODES * HID];
__device__ __nv_bfloat16 g_Al[N_NODES * HID];
// bf16 split weights [N][K]
__device__ __nv_bfloat16 g_B1h[HID * IN_C];
__device__ __nv_bfloat16 g_B1l[HID * IN_C];
__device__ __nv_bfloat16 g_B2h[OUT_C * HID];
__device__ __nv_bfloat16 g_B2l[OUT_C * HID];

// ---------------------------------------------------------------------------
// Helpers
// ---------------------------------------------------------------------------
__device__ __forceinline__ uint32_t smem_to_u32(const void* p) {
    uint32_t a;
    asm("{ .reg .u64 t; cvta.to.shared.u64 t, %1; cvt.u32.u64 %0, t; }"
        : "=r"(a) : "l"(p));
    return a;
}
__device__ __forceinline__ void ldsm_x4(uint32_t* r, uint32_t addr) {
    asm volatile("ldmatrix.sync.aligned.m8n8.x4.shared.b16 {%0,%1,%2,%3}, [%4];"
                 : "=r"(r[0]), "=r"(r[1]), "=r"(r[2]), "=r"(r[3]) : "r"(addr));
}
__device__ __forceinline__ void ldsm_x2(uint32_t* r, uint32_t addr) {
    asm volatile("ldmatrix.sync.aligned.m8n8.x2.shared.b16 {%0,%1}, [%2];"
                 : "=r"(r[0]), "=r"(r[1]) : "r"(addr));
}
__device__ __forceinline__ void mma_bf16(float* d, const uint32_t* a, const uint32_t* b) {
    asm volatile("mma.sync.aligned.m16n8k16.row.col.f32.bf16.bf16.f32 "
                 "{%0,%1,%2,%3}, {%4,%5,%6,%7}, {%8,%9}, {%0,%1,%2,%3};"
                 : "+f"(d[0]), "+f"(d[1]), "+f"(d[2]), "+f"(d[3])
                 : "r"(a[0]), "r"(a[1]), "r"(a[2]), "r"(a[3]),
                   "r"(b[0]), "r"(b[1]));
}
__device__ __forceinline__ void cp16(uint32_t dst, const void* src, int bytes) {
    asm volatile("cp.async.ca.shared.global [%0], [%1], 16, %2;"
                 :: "r"(dst), "l"(src), "r"(bytes) : "memory");
}
#define CP_COMMIT() asm volatile("cp.async.commit_group;" ::: "memory")
template <int NG> __device__ __forceinline__ void cp_wait() {
    asm volatile("cp.async.wait_group %0;" :: "n"(NG) : "memory");
}

__device__ __forceinline__ void bf16_split(float x, unsigned short& hi, unsigned short& lo) {
    __nv_bfloat16 h = __float2bfloat16(x);
    float r = x - __bfloat162float(h);
    __nv_bfloat16 l = __float2bfloat16(r);
    hi = __bfloat16_as_ushort(h);
    lo = __bfloat16_as_ushort(l);
}
__device__ __forceinline__ int load_idx(const void* p, long long i) {
    if (g_idx64) return (int)((const long long*)p)[i];
    return ((const int*)p)[i];
}
__device__ __forceinline__ void red_add_v4(float* p, float x, float y, float z, float w) {
    asm volatile("red.global.add.v4.f32 [%0], {%1,%2,%3,%4};"
                 :: "l"(p), "f"(x), "f"(y), "f"(z), "f"(w) : "memory");
}

// ---------------------------------------------------------------------------
// Prolog kernels
// ---------------------------------------------------------------------------
__global__ void k_detect(const void* ei) {
    if (threadIdx.x == 0 && blockIdx.x == 0) {
        const long long* p = (const long long*)ei;
        int ok = 1;
        for (int i = 0; i < 256; i++) {
            long long v = p[i];
            if (v < 0 || v >= N_NODES) { ok = 0; break; }
        }
        g_idx64 = ok;
    }
}

__global__ void k_zero() {
    int i = blockIdx.x * blockDim.x + threadIdx.x;
    if (i < N_NODES) g_deg[i] = 0.f;
    if (i < N_GRAPHS * F_TOT) g_pool[i] = 0.f;
    if (i < N_GRAPHS) g_cnt[i] = 0.f;
}

__global__ void k_splitW(const float* __restrict__ W1, const float* __restrict__ W2) {
    int i = blockIdx.x * blockDim.x + threadIdx.x;
    if (i < IN_C * HID) {
        int k = i / HID, n = i % HID;
        unsigned short hi, lo;
        bf16_split(W1[i], hi, lo);
        g_B1h[n * IN_C + k] = __ushort_as_bfloat16(hi);
        g_B1l[n * IN_C + k] = __ushort_as_bfloat16(lo);
    } else {
        int j = i - IN_C * HID;
        if (j < HID * OUT_C) {
            int k = j / OUT_C, n = j % OUT_C;
            unsigned short hi, lo;
            bf16_split(W2[j], hi, lo);
            g_B2h[n * HID + k] = __ushort_as_bfloat16(hi);
            g_B2l[n * HID + k] = __ushort_as_bfloat16(lo);
        }
    }
}

__global__ void k_deg(const void* __restrict__ ei) {
    int e = blockIdx.x * blockDim.x + threadIdx.x;
    if (e < N_EDGES) {
        int d = load_idx(ei, (long long)N_EDGES + e);
        atomicAdd(&g_deg[d], 1.0f);
    }
}
__global__ void k_dinv() {
    int i = blockIdx.x * blockDim.x + threadIdx.x;
    if (i < N_NODES) g_dinv[i] = rsqrtf(g_deg[i] + 1.0f);
}
__global__ void k_cnt(const void* __restrict__ batch) {
    int i = blockIdx.x * blockDim.x + threadIdx.x;
    if (i < N_NODES) {
        int g = load_idx(batch, i);
        atomicAdd(&g_cnt[g], 1.0f);
    }
}

// Exclusive scan of deg -> g_off / g_cursor. Single block, 1024 threads.
__global__ void k_scan() {
    __shared__ int swarp[32];
    __shared__ int s_carry;
    int tid = threadIdx.x, lane = tid & 31, wid = tid >> 5;
    if (tid == 0) s_carry = 0;
    __syncthreads();
    for (int base = 0; base < N_NODES; base += 1024) {
        int i = base + tid;
        int v = (i < N_NODES) ? (int)g_deg[i] : 0;
        int incl = v;
#pragma unroll
        for (int o = 1; o < 32; o <<= 1) {
            int t = __shfl_up_sync(0xFFFFFFFFu, incl, o);
            if (lane >= o) incl += t;
        }
        if (lane == 31) swarp[wid] = incl;
        __syncthreads();
        if (wid == 0) {
            int ws = swarp[lane];
            int wincl = ws;
#pragma unroll
            for (int o = 1; o < 32; o <<= 1) {
                int t = __shfl_up_sync(0xFFFFFFFFu, wincl, o);
                if (lane >= o) wincl += t;
            }
            swarp[lane] = wincl - ws;
        }
        __syncthreads();
        int ex = s_carry + swarp[wid] + incl - v;
        if (i < N_NODES) { g_off[i] = ex; g_cursor[i] = ex; }
        __syncthreads();
        if (tid == 1023) s_carry = ex + v;
        __syncthreads();
    }
    if (threadIdx.x == 0) g_off[N_NODES] = s_carry;
}

__global__ void k_fill(const void* __restrict__ ei) {
    int e = blockIdx.x * blockDim.x + threadIdx.x;
    if (e >= N_EDGES) return;
    int s = load_idx(ei, e);
    int d = load_idx(ei, (long long)N_EDGES + e);
    int p = atomicAdd(&g_cursor[d], 1);
    g_csr[p]  = s;
    g_csrw[p] = g_dinv[s] * g_dinv[d];
}

// ---------------------------------------------------------------------------
// Pipelined bf16-split GEMM, templated on A source:
//   AFP32=true : A fp32 [M,K]; staged via cp.async into single-buffered A32
//                region, split to bf16 hi/lo in smem per chunk.
//   AFP32=false: A pre-split bf16 hi/lo arrays.
// Tile 128x128, BK=32, cp.async double-buffered bf16 stage (Ah|Al|Bh|Bl).
// ---------------------------------------------------------------------------
#define PITCH    80
#define TILE_B   (128 * PITCH)        // 10240
#define STAGE_B  (4 * TILE_B)         // 40960
#define A32_B    16384                // 128 x 32 fp32

template <bool AFP32>
__global__ void __launch_bounds__(256, 2)
k_gemm(const float* __restrict__ A32,
       const __nv_bfloat16* __restrict__ Ah, const __nv_bfloat16* __restrict__ Al,
       const __nv_bfloat16* __restrict__ Bh, const __nv_bfloat16* __restrict__ Bl,
       float* __restrict__ C, int M, int Nld, int K) {
    extern __shared__ char smem[];
    const int tid  = threadIdx.x;
    const int lane = tid & 31;
    const int wid  = tid >> 5;
    const int wm   = (wid & 1) * 64;
    const int wn   = (wid >> 1) * 32;
    const int mBase = blockIdx.y * 128;
    const int nBase = blockIdx.x * 128;
    const uint32_t sbase = smem_to_u32(smem);
    const uint32_t sA32  = sbase;                       // only used if AFP32
    const uint32_t sStg  = AFP32 ? sbase + A32_B : sbase;

    float acc[4][4][4];
#pragma unroll
    for (int i = 0; i < 4; i++)
#pragma unroll
        for (int j = 0; j < 4; j++)
#pragma unroll
            for (int q = 0; q < 4; q++) acc[i][j][q] = 0.f;

    const int aRow = lane & 15;
    const int aK   = (lane >> 4) * 16;
    const int bRow = lane & 7;
    const int bK   = ((lane & 15) >> 3) * 16;

    const int nch = K >> 5;

    auto stage = [&](int ch, int buf) {
        const int k0 = ch << 5;
        const uint32_t sb = sStg + buf * STAGE_B;
        if (AFP32) {
            // fp32 A: 128 rows x 32 floats = 8 x 16B per row
#pragma unroll
            for (int t = 0; t < 4; t++) {
                int idx = t * 256 + tid;          // 0..1023
                int m = idx >> 3, q = idx & 7;
                int gm = mBase + m;
                int ok = (gm < M) ? 16 : 0;
                if (!ok) gm = 0;
                cp16(sA32 + m * 128 + q * 16, A32 + (size_t)gm * K + k0 + q * 4, ok);
            }
            // B bf16 hi/lo: 128 rows x 4 x 16B each
#pragma unroll
            for (int t = 0; t < 2; t++) {
                int idx = t * 256 + tid;          // 0..511
                int n = idx >> 2, q = idx & 3;
                uint32_t so = sb + 2 * TILE_B + n * PITCH + q * 16;
                const size_t gb = (size_t)(nBase + n) * K + k0 + q * 8;
                cp16(so,          Bh + gb, 16);
                cp16(so + TILE_B, Bl + gb, 16);
            }
        } else {
#pragma unroll
            for (int t = 0; t < 2; t++) {
                int idx = t * 256 + tid;          // 0..511
                int m = idx >> 2, q = idx & 3;
                uint32_t so = sb + m * PITCH + q * 16;
                int gm = mBase + m;
                int okA = (gm < M) ? 16 : 0;
                if (!okA) gm = 0;
                const size_t ga = (size_t)gm * K + k0 + q * 8;
                cp16(so,              Ah + ga, okA);
                cp16(so + TILE_B,     Al + ga, okA);
                const size_t gb = (size_t)(nBase + m) * K + k0 + q * 8;
                cp16(so + 2 * TILE_B, Bh + gb, 16);
                cp16(so + 3 * TILE_B, Bl + gb, 16);
            }
        }
    };

    stage(0, 0); CP_COMMIT();
    for (int ch = 0; ch < nch; ch++) {
        const int buf = ch & 1;
        const uint32_t sb = sStg + buf * STAGE_B;

        if (AFP32) {
            cp_wait<0>();
            __syncthreads();
            // split A32 -> Ah/Al of this stage buffer
#pragma unroll
            for (int t = 0; t < 4; t++) {
                int idx = t * 256 + tid;          // 0..1023 float4s
                int m = idx >> 3, q = idx & 7;
                float4 v = *(const float4*)(smem + (m * 128 + q * 16));
                unsigned short h0, l0, h1, l1, h2, l2, h3, l3;
                bf16_split(v.x, h0, l0); bf16_split(v.y, h1, l1);
                bf16_split(v.z, h2, l2); bf16_split(v.w, h3, l3);
                uint2 hw, lw;
                hw.x = ((uint32_t)h1 << 16) | h0;  hw.y = ((uint32_t)h3 << 16) | h2;
                lw.x = ((uint32_t)l1 << 16) | l0;  lw.y = ((uint32_t)l3 << 16) | l2;
                char* so = smem + A32_B + buf * STAGE_B + m * PITCH + q * 8;
                *(uint2*)(so)          = hw;
                *(uint2*)(so + TILE_B) = lw;
            }
            __syncthreads();
            if (ch + 1 < nch) { stage(ch + 1, buf ^ 1); CP_COMMIT(); }
        } else {
            if (ch + 1 < nch) { stage(ch + 1, buf ^ 1); CP_COMMIT(); cp_wait<1>(); }
            else              { cp_wait<0>(); }
            __syncthreads();
        }

#pragma unroll
        for (int ks = 0; ks < 2; ks++) {
            const int koff = ks * 32;
            uint32_t bhf[4][2], blf[4][2];
#pragma unroll
            for (int nf = 0; nf < 4; nf++) {
                uint32_t ro = sb + 2 * TILE_B + (uint32_t)(wn + nf * 8 + bRow) * PITCH + koff + bK;
                ldsm_x2(bhf[nf], ro);
                ldsm_x2(blf[nf], ro + TILE_B);
            }
#pragma unroll
            for (int mf = 0; mf < 4; mf++) {
                uint32_t ah[4], al[4];
                uint32_t ro = sb + (uint32_t)(wm + mf * 16 + aRow) * PITCH + koff + aK;
                ldsm_x4(ah, ro);
                ldsm_x4(al, ro + TILE_B);
#pragma unroll
                for (int nf = 0; nf < 4; nf++) {
                    mma_bf16(acc[mf][nf], ah, bhf[nf]);
                    mma_bf16(acc[mf][nf], ah, blf[nf]);
                    mma_bf16(acc[mf][nf], al, bhf[nf]);
                }
            }
        }
        if (!AFP32) __syncthreads();
        // AFP32 path: top-of-loop cp_wait + syncthreads provides the barrier.
        else __syncthreads();
    }

#pragma unroll
    for (int mf = 0; mf < 4; mf++) {
        int r0 = mBase + wm + mf * 16 + (lane >> 2);
#pragma unroll
        for (int nf = 0; nf < 4; nf++) {
            int c0 = nBase + wn + nf * 8 + (lane & 3) * 2;
            if (r0 < M)
                *(float2*)(C + (size_t)r0 * Nld + c0) =
                    make_float2(acc[mf][nf][0], acc[mf][nf][1]);
            if (r0 + 8 < M)
                *(float2*)(C + (size_t)(r0 + 8) * Nld + c0) =
                    make_float2(acc[mf][nf][2], acc[mf][nf][3]);
        }
    }
}

// ---------------------------------------------------------------------------
// Fused CSR aggregation (warp per node): selfloop + gather + relu + bias +
// node_embed + pool red + optional bf16 split for next GEMM.
// ---------------------------------------------------------------------------
template <int SH, int COFF, bool SPLIT_OUT>
__global__ void __launch_bounds__(256)
k_agg(const float* __restrict__ h, const float* __restrict__ bias,
      const void* __restrict__ batch, float* __restrict__ out_node) {
    const int gw   = (blockIdx.x * blockDim.x + threadIdx.x) >> 5;
    const int lane = threadIdx.x & 31;
    if (gw >= N_NODES) return;
    const int i = gw;
    constexpr int C = 1 << (SH - 5);
    const float4* h4 = (const float4*)h;

    float4 acc[C];
    const float di = g_dinv[i];
    const float s2 = di * di;
#pragma unroll
    for (int c = 0; c < C; c++) {
        float4 v = h4[((size_t)i << SH) + lane + c * 32];
        acc[c] = make_float4(v.x * s2, v.y * s2, v.z * s2, v.w * s2);
    }

    int j  = g_off[i];
    const int je = g_off[i + 1];
    for (; j + 1 < je; j += 2) {
        int   s0 = g_csr[j],     s1 = g_csr[j + 1];
        float w0 = g_csrw[j],    w1 = g_csrw[j + 1];
        float4 v0[C], v1[C];
#pragma unroll
        for (int c = 0; c < C; c++) {
            v0[c] = h4[((size_t)s0 << SH) + lane + c * 32];
            v1[c] = h4[((size_t)s1 << SH) + lane + c * 32];
        }
#pragma unroll
        for (int c = 0; c < C; c++) {
            acc[c].x += v0[c].x * w0 + v1[c].x * w1;
            acc[c].y += v0[c].y * w0 + v1[c].y * w1;
            acc[c].z += v0[c].z * w0 + v1[c].z * w1;
            acc[c].w += v0[c].w * w0 + v1[c].w * w1;
        }
    }
    if (j < je) {
        int   s0 = g_csr[j];
        float w0 = g_csrw[j];
#pragma unroll
        for (int c = 0; c < C; c++) {
            float4 v = h4[((size_t)s0 << SH) + lane + c * 32];
            acc[c].x += v.x * w0; acc[c].y += v.y * w0;
            acc[c].z += v.z * w0; acc[c].w += v.w * w0;
        }
    }

    const int g = load_idx(batch, i);
    const float4* bias4 = (const float4*)bias;
#pragma unroll
    for (int c = 0; c < C; c++) {
        float4 bb = bias4[lane + c * 32];
        float4 a;
        a.x = fmaxf(acc[c].x + bb.x, 0.f);
        a.y = fmaxf(acc[c].y + bb.y, 0.f);
        a.z = fmaxf(acc[c].z + bb.z, 0.f);
        a.w = fmaxf(acc[c].w + bb.w, 0.f);
        ((float4*)out_node)[(size_t)i * F4_TOT + COFF + lane + c * 32] = a;
        red_add_v4(g_pool + (((size_t)g * F4_TOT + COFF + lane + c * 32) << 2),
                   a.x, a.y, a.z, a.w);
        if (SPLIT_OUT) {
            unsigned short h0, l0, h1, l1, h2, l2, h3, l3;
            bf16_split(a.x, h0, l0); bf16_split(a.y, h1, l1);
            bf16_split(a.z, h2, l2); bf16_split(a.w, h3, l3);
            uint2 hw, lw;
            hw.x = ((uint32_t)h1 << 16) | h0;  hw.y = ((uint32_t)h3 << 16) | h2;
            lw.x = ((uint32_t)l1 << 16) | l0;  lw.y = ((uint32_t)l3 << 16) | l2;
            size_t o = ((size_t)i << SH) + lane + c * 32;
            ((uint2*)g_Ah)[o] = hw;
            ((uint2*)g_Al)[o] = lw;
        }
    }
}

__global__ void k_pooldiv(float* __restrict__ out_graph) {
    int tid = blockIdx.x * blockDim.x + threadIdx.x;
    if (tid >= N_GRAPHS * F4_TOT) return;
    int g = tid / F4_TOT;
    float inv = 1.0f / fmaxf(g_cnt[g], 1.0f);
    float4 v = ((float4*)g_pool)[tid];
    v.x *= inv; v.y *= inv; v.z *= inv; v.w *= inv;
    ((float4*)out_graph)[tid] = v;
}

// ---------------------------------------------------------------------------
// Launch
// ---------------------------------------------------------------------------
extern "C" void kernel_launch(void* const* d_in, const int* in_sizes, int n_in,
                              void* d_out, int out_size) {
    const float* x     = (const float*)d_in[0];
    const void*  ei    = d_in[1];
    const void*  batch = d_in[2];
    const float *W1, *b1, *W2, *b2;
    if (n_in >= 8) {
        W1 = (const float*)d_in[4]; b1 = (const float*)d_in[5];
        W2 = (const float*)d_in[6]; b2 = (const float*)d_in[7];
    } else {
        W1 = (const float*)d_in[3]; b1 = (const float*)d_in[4];
        W2 = (const float*)d_in[5]; b2 = (const float*)d_in[6];
    }
    float* out       = (float*)d_out;
    float* out_graph = out;
    float* out_node  = out + (size_t)N_GRAPHS * F_TOT;

    void *p_h, *p_Ah, *p_Al, *p_B1h, *p_B1l, *p_B2h, *p_B2l;
    cudaGetSymbolAddress(&p_h,   g_h);
    cudaGetSymbolAddress(&p_Ah,  g_Ah);
    cudaGetSymbolAddress(&p_Al,  g_Al);
    cudaGetSymbolAddress(&p_B1h, g_B1h);
    cudaGetSymbolAddress(&p_B1l, g_B1l);
    cudaGetSymbolAddress(&p_B2h, g_B2h);
    cudaGetSymbolAddress(&p_B2l, g_B2l);
    float* h = (float*)p_h;

    cudaFuncSetAttribute(k_gemm<true>,  cudaFuncAttributeMaxDynamicSharedMemorySize,
                         A32_B + 2 * STAGE_B);
    cudaFuncSetAttribute(k_gemm<false>, cudaFuncAttributeMaxDynamicSharedMemorySize,
                         2 * STAGE_B);

    // Side stream for the CSR prolog (created once; first call is the
    // non-captured correctness run, so creation never happens inside capture).
    static cudaStream_t s_side = nullptr;
    static cudaEvent_t  s_fork = nullptr, s_join = nullptr;
    if (!s_side) {
        cudaStreamCreateWithFlags(&s_side, cudaStreamNonBlocking);
        cudaEventCreateWithFlags(&s_fork, cudaEventDisableTiming);
        cudaEventCreateWithFlags(&s_join, cudaEventDisableTiming);
    }

    const int T = 256;
    k_zero<<<(N_GRAPHS * F_TOT + T - 1) / T, T>>>();

    // ---- fork: CSR build on side stream, GEMM1 on main ----
    cudaEventRecord(s_fork, 0);
    cudaStreamWaitEvent(s_side, s_fork, 0);
    k_detect<<<1, 32, 0, s_side>>>(ei);
    k_deg<<<(N_EDGES + T - 1) / T, T, 0, s_side>>>(ei);
    k_dinv<<<(N_NODES + T - 1) / T, T, 0, s_side>>>();
    k_cnt<<<(N_NODES + T - 1) / T, T, 0, s_side>>>(batch);
    k_scan<<<1, 1024, 0, s_side>>>();
    k_fill<<<(N_EDGES + T - 1) / T, T, 0, s_side>>>(ei);
    cudaEventRecord(s_join, s_side);

    k_splitW<<<(IN_C * HID + HID * OUT_C + T - 1) / T, T>>>(W1, W2);
    // Layer 1 GEMM: h = x @ W1 (A split fused, fp32 input)
    k_gemm<true><<<dim3(HID / 128, (N_NODES + 127) / 128), 256, A32_B + 2 * STAGE_B>>>(
        x, nullptr, nullptr,
        (const __nv_bfloat16*)p_B1h, (const __nv_bfloat16*)p_B1l,
        h, N_NODES, HID, IN_C);

    cudaStreamWaitEvent(0, s_join, 0);   // join CSR before aggregation

    // ---- Layer 1 aggregate ----
    k_agg<6, 0, true><<<(N_NODES * 32 + T - 1) / T, T>>>(h, b1, batch, out_node);

    // ---- Layer 2 GEMM: h2pre = h1 @ W2 (A pre-split by agg1 epilogue) ----
    k_gemm<false><<<dim3(OUT_C / 128, (N_NODES + 127) / 128), 256, 2 * STAGE_B>>>(
        nullptr, (const __nv_bfloat16*)p_Ah, (const __nv_bfloat16*)p_Al,
        (const __nv_bfloat16*)p_B2h, (const __nv_bfloat16*)p_B2l,
        h, N_NODES, OUT_C, HID);

    // ---- Layer 2 aggregate ----
    k_agg<5, 64, false><<<(N_NODES * 32 + T - 1) / T, T>>>(h, b2, batch, out_node);

    // ---- Pool means ----
    k_pooldiv<<<(N_GRAPHS * F4_TOT + T - 1) / T, T>>>(out_graph);
}